// round 1
// baseline (speedup 1.0000x reference)
#include <cuda_runtime.h>
#include <math.h>

#define NU 50000
#define NI 100000
#define NN 150000
#define D  64
#define NINT 128
#define NE 3000000
#define NL 2

// ---------------- scratch (device globals; no allocation allowed) ----------
__device__ __align__(256) float d_emb[NN * D];
__device__ __align__(256) float d_gnn[NN * D];
__device__ __align__(256) float d_int[NN * D];
__device__ __align__(256) float d_agg[NN * D];
__device__ __align__(256) float d_dis[NN];      // deg accumulation -> d^-1/2
__device__ __align__(256) float d_invn_g[NN];
__device__ __align__(256) float d_invn_i[NN];
__device__ __align__(256) float d_rs_g[NN];     // row_sum -> d_inv (in place)
__device__ __align__(256) float d_rs_i[NN];
__device__ __align__(256) float d_alpha_g[NE];
__device__ __align__(256) float d_alpha_i[NE];

// ---------------------------------------------------------------------------
__global__ void k_init(const float* __restrict__ ue, const float* __restrict__ ie,
                       float* __restrict__ out) {
    int i = blockIdx.x * blockDim.x + threadIdx.x;   // float4 index
    const int n4  = NN * D / 4;
    const int nu4 = NU * D / 4;
    if (i >= n4) return;
    float4 v = (i < nu4) ? ((const float4*)ue)[i] : ((const float4*)ie)[i - nu4];
    ((float4*)d_emb)[i] = v;
    ((float4*)out)[i]   = v;
}

__global__ void k_zero_deg() {
    int i = blockIdx.x * blockDim.x + threadIdx.x;
    if (i < NN) d_dis[i] = 0.0f;
}

__global__ void k_deg(const int* __restrict__ h) {
    int e = blockIdx.x * blockDim.x + threadIdx.x;
    if (e < NE) atomicAdd(&d_dis[h[e]], 1.0f);
}

__global__ void k_dis() {
    int i = blockIdx.x * blockDim.x + threadIdx.x;
    if (i >= NN) return;
    float dg = d_dis[i];
    d_dis[i] = (dg > 0.0f) ? (1.0f / sqrtf(dg)) : 0.0f;
}

__global__ void k_zero_layer() {
    int i = blockIdx.x * blockDim.x + threadIdx.x;
    const int n4 = NN * D / 4;
    float4 z = make_float4(0.f, 0.f, 0.f, 0.f);
    if (i < n4) {
        ((float4*)d_gnn)[i] = z;
        ((float4*)d_agg)[i] = z;
    }
    if (i < NN) {
        d_rs_g[i] = 0.0f;
        d_rs_i[i] = 0.0f;
    }
}

__device__ __forceinline__ void red_add_v4(float* dst, float a, float b, float c, float d) {
    asm volatile("red.global.add.v4.f32 [%0], {%1,%2,%3,%4};"
                 :: "l"(dst), "f"(a), "f"(b), "f"(c), "f"(d) : "memory");
}

// gnn[h] += dis[h]*dis[t] * emb[t] ; 16 lanes per edge (float4 each)
__global__ void k_spmm_gnn(const int* __restrict__ h, const int* __restrict__ t) {
    int gid = blockIdx.x * blockDim.x + threadIdx.x;
    int e = gid >> 4, s = gid & 15;
    if (e >= NE) return;
    int hh = h[e], tt = t[e];
    float val = d_dis[hh] * d_dis[tt];
    float4 v = *(const float4*)(d_emb + tt * D + s * 4);
    red_add_v4(d_gnn + hh * D + s * 4, val * v.x, val * v.y, val * v.z, val * v.w);
}

// warp-per-row softmax-intent projection. Blocks [0,6250) are users (8 rows/blk,
// 50000/8=6250 exact), the rest items.
__global__ void k_intent(const float* __restrict__ uW, const float* __restrict__ iW) {
    __shared__ float WT[NINT][D + 1];   // transposed, padded (65 == 1 mod 32)
    __shared__ float rowbuf[8][D];
    int wid = threadIdx.x >> 5, lane = threadIdx.x & 31;
    int row0 = blockIdx.x * 8;
    const float* W = (row0 < NU) ? uW : iW;
    for (int idx = threadIdx.x; idx < D * NINT; idx += blockDim.x) {
        int dd = idx / NINT, j = idx % NINT;
        WT[j][dd] = W[idx];
    }
    __syncthreads();
    int row = row0 + wid;
    if (row >= NN) return;
    const float* src = d_emb + row * D;
    rowbuf[wid][lane]      = src[lane];
    rowbuf[wid][lane + 32] = src[lane + 32];
    __syncwarp();

    // phase 1: logits j = lane + 32*s
    float lg[4] = {0.f, 0.f, 0.f, 0.f};
    #pragma unroll
    for (int dd = 0; dd < D; dd++) {
        float rb = rowbuf[wid][dd];
        #pragma unroll
        for (int s = 0; s < 4; s++) lg[s] += rb * WT[s * 32 + lane][dd];
    }
    // softmax over 128
    float m = fmaxf(fmaxf(lg[0], lg[1]), fmaxf(lg[2], lg[3]));
    #pragma unroll
    for (int o = 16; o >= 1; o >>= 1) m = fmaxf(m, __shfl_xor_sync(0xffffffffu, m, o));
    float p[4], ssum = 0.f;
    #pragma unroll
    for (int s = 0; s < 4; s++) { p[s] = expf(lg[s] - m); ssum += p[s]; }
    #pragma unroll
    for (int o = 16; o >= 1; o >>= 1) ssum += __shfl_xor_sync(0xffffffffu, ssum, o);
    float inv = 1.0f / ssum;
    #pragma unroll
    for (int s = 0; s < 4; s++) p[s] *= inv;

    // phase 2: out[d] = sum_j p_j * W[d][j]; lane owns d = lane, lane+32
    float o0 = 0.f, o1 = 0.f;
    #pragma unroll
    for (int s = 0; s < 4; s++) {
        #pragma unroll
        for (int l = 0; l < 32; l++) {
            float pv = __shfl_sync(0xffffffffu, p[s], l);
            int j = s * 32 + l;
            o0 += pv * WT[j][lane];
            o1 += pv * WT[j][lane + 32];
        }
    }
    d_int[row * D + lane]      = o0;
    d_int[row * D + lane + 32] = o1;
}

// inverse l2 norms of gnn and int rows (warp per node)
__global__ void k_norms() {
    int g = (blockIdx.x * blockDim.x + threadIdx.x) >> 5;
    int lane = threadIdx.x & 31;
    if (g >= NN) return;
    const float* gp = d_gnn + g * D;
    const float* ip = d_int + g * D;
    float a = gp[lane], b = gp[lane + 32];
    float sg = a * a + b * b;
    a = ip[lane]; b = ip[lane + 32];
    float si = a * a + b * b;
    #pragma unroll
    for (int o = 16; o >= 1; o >>= 1) {
        sg += __shfl_xor_sync(0xffffffffu, sg, o);
        si += __shfl_xor_sync(0xffffffffu, si, o);
    }
    if (lane == 0) {
        d_invn_g[g] = 1.0f / fmaxf(sqrtf(sg), 1e-8f);
        d_invn_i[g] = 1.0f / fmaxf(sqrtf(si), 1e-8f);
    }
}

// per-edge cosine alphas for both sources + scalar row-sum reductions
__global__ void k_alpha(const int* __restrict__ h, const int* __restrict__ t) {
    int gid = blockIdx.x * blockDim.x + threadIdx.x;
    int e = gid >> 4, s = gid & 15;
    if (e >= NE) return;
    int hh = h[e], tt = t[e];
    float4 gh = *(const float4*)(d_gnn + hh * D + s * 4);
    float4 gt = *(const float4*)(d_gnn + tt * D + s * 4);
    float4 ih = *(const float4*)(d_int + hh * D + s * 4);
    float4 it = *(const float4*)(d_int + tt * D + s * 4);
    float dg = gh.x * gt.x + gh.y * gt.y + gh.z * gt.z + gh.w * gt.w;
    float di = ih.x * it.x + ih.y * it.y + ih.z * it.z + ih.w * it.w;
    #pragma unroll
    for (int o = 8; o >= 1; o >>= 1) {
        dg += __shfl_xor_sync(0xffffffffu, dg, o);
        di += __shfl_xor_sync(0xffffffffu, di, o);
    }
    if (s == 0) {
        float ag = (dg * d_invn_g[hh] * d_invn_g[tt] + 1.0f) * 0.5f;
        float ai = (di * d_invn_i[hh] * d_invn_i[tt] + 1.0f) * 0.5f;
        d_alpha_g[e] = ag;
        d_alpha_i[e] = ai;
        atomicAdd(&d_rs_g[hh], ag);
        atomicAdd(&d_rs_i[hh], ai);
    }
}

__global__ void k_dinv() {
    int i = blockIdx.x * blockDim.x + threadIdx.x;
    if (i >= NN) return;
    float a = d_rs_g[i], b = d_rs_i[i];
    d_rs_g[i] = (a > 0.0f) ? (1.0f / a) : 0.0f;
    d_rs_i[i] = (b > 0.0f) ? (1.0f / b) : 0.0f;
}

// fused adaptive SpMM: agg[h] += (dinv_g[h]*alpha_g + dinv_i[h]*alpha_i) * emb[t]
__global__ void k_spmm2(const int* __restrict__ h, const int* __restrict__ t) {
    int gid = blockIdx.x * blockDim.x + threadIdx.x;
    int e = gid >> 4, s = gid & 15;
    if (e >= NE) return;
    int hh = h[e], tt = t[e];
    float val = d_rs_g[hh] * d_alpha_g[e] + d_rs_i[hh] * d_alpha_i[e];
    float4 v = *(const float4*)(d_emb + tt * D + s * 4);
    red_add_v4(d_agg + hh * D + s * 4, val * v.x, val * v.y, val * v.z, val * v.w);
}

// emb = gnn + int + agg + emb ; acc += emb
__global__ void k_combine(float* __restrict__ out) {
    int i = blockIdx.x * blockDim.x + threadIdx.x;
    const int n4 = NN * D / 4;
    if (i >= n4) return;
    float4 e0 = ((const float4*)d_emb)[i];
    float4 g  = ((const float4*)d_gnn)[i];
    float4 it = ((const float4*)d_int)[i];
    float4 ag = ((const float4*)d_agg)[i];
    float4 en = make_float4(e0.x + g.x + it.x + ag.x,
                            e0.y + g.y + it.y + ag.y,
                            e0.z + g.z + it.z + ag.z,
                            e0.w + g.w + it.w + ag.w);
    ((float4*)d_emb)[i] = en;
    float4 o = ((float4*)out)[i];
    o.x += en.x; o.y += en.y; o.z += en.z; o.w += en.w;
    ((float4*)out)[i] = o;
}

// ---------------------------------------------------------------------------
extern "C" void kernel_launch(void* const* d_in, const int* in_sizes, int n_in,
                              void* d_out, int out_size) {
    const float* ue = (const float*)d_in[0];
    const float* ie = (const float*)d_in[1];
    const float* uW = (const float*)d_in[2];
    const float* iW = (const float*)d_in[3];
    const int*   h  = (const int*)d_in[4];
    const int*   t  = (const int*)d_in[5];
    float* out = (float*)d_out;

    const int TB = 256;
    const int n4 = NN * D / 4;                 // 2.4M float4
    const int gN4 = (n4 + TB - 1) / TB;
    const int gNN = (NN + TB - 1) / TB;
    const int gE  = (NE + TB - 1) / TB;
    const int gE16 = ((long long)NE * 16 + TB - 1) / TB;
    const int gNodeWarp = (NN * 32 + TB - 1) / TB;

    k_init<<<gN4, TB>>>(ue, ie, out);
    k_zero_deg<<<gNN, TB>>>();
    k_deg<<<gE, TB>>>(h);
    k_dis<<<gNN, TB>>>();

    for (int layer = 0; layer < NL; layer++) {
        k_zero_layer<<<gN4, TB>>>();
        k_spmm_gnn<<<gE16, TB>>>(h, t);
        k_intent<<<NN / 8, TB>>>(uW, iW);
        k_norms<<<gNodeWarp, TB>>>();
        k_alpha<<<gE16, TB>>>(h, t);
        k_dinv<<<gNN, TB>>>();
        k_spmm2<<<gE16, TB>>>(h, t);
        k_combine<<<gN4, TB>>>(out);
    }
}